// round 1
// baseline (speedup 1.0000x reference)
#include <cuda_runtime.h>
#include <cstdint>

// Problem constants (match reference_code)
#define N_NODES 150000
#define DIM 64
#define NE 4800000
#define LN_EPS 1e-5f
#define LEAKY_SLOPE 0.5f

// Scratch: two N x D fp32 buffers (38.4 MB each). __device__ globals => no allocation.
__device__ float g_tmp[(size_t)N_NODES * DIM];
__device__ float g_h[(size_t)N_NODES * DIM];

// ---------------------------------------------------------------------------
// Zero a buffer (float4-wide)
// ---------------------------------------------------------------------------
__global__ __launch_bounds__(256) void zero_kernel(float4* __restrict__ p, int n4) {
    int i = blockIdx.x * blockDim.x + threadIdx.x;
    if (i < n4) p[i] = make_float4(0.f, 0.f, 0.f, 0.f);
}

// ---------------------------------------------------------------------------
// Vectored fp32 reduction (sm_90+): 4 floats, one L2 atomic op, no return value
// ---------------------------------------------------------------------------
__device__ __forceinline__ void red_add_f32x4(float4* addr, float4 v) {
    asm volatile("red.global.add.v4.f32 [%0], {%1, %2, %3, %4};"
                 :: "l"(addr), "f"(v.x), "f"(v.y), "f"(v.z), "f"(v.w)
                 : "memory");
}

// ---------------------------------------------------------------------------
// Scatter SpMM:  y[dst[e]] += vals[e] * f(x[src[e]])   for all edges e
//   f = identity or LeakyReLU(0.5) applied to the gathered input (fused act)
//   16 threads per edge, one float4 per thread -> coalesced 256B row accesses
// ---------------------------------------------------------------------------
template <bool LEAKY_IN>
__global__ __launch_bounds__(256) void spmm_scatter(
    const float4* __restrict__ x,
    const float*  __restrict__ vals,
    const int*    __restrict__ src,
    const int*    __restrict__ dst,
    float4*       __restrict__ y)
{
    int t    = blockIdx.x * blockDim.x + threadIdx.x;   // < NE*16 = 76.8M, fits int
    int edge = t >> 4;
    int lane = t & 15;
    if (edge >= NE) return;

    int   s = __ldg(src  + edge);
    int   d = __ldg(dst  + edge);
    float v = __ldg(vals + edge);

    float4 xv = __ldg(x + s * 16 + lane);
    if (LEAKY_IN) {
        xv.x = xv.x > 0.f ? xv.x : LEAKY_SLOPE * xv.x;
        xv.y = xv.y > 0.f ? xv.y : LEAKY_SLOPE * xv.y;
        xv.z = xv.z > 0.f ? xv.z : LEAKY_SLOPE * xv.z;
        xv.w = xv.w > 0.f ? xv.w : LEAKY_SLOPE * xv.w;
    }
    float4 r = make_float4(v * xv.x, v * xv.y, v * xv.z, v * xv.w);
    red_add_f32x4(y + d * 16 + lane, r);
}

// ---------------------------------------------------------------------------
// Final: out = LayerNorm(h) * gamma + beta + ego        (warp per node, D=64)
// Each lane owns 2 columns (float2); mean/var via warp shuffles.
// ---------------------------------------------------------------------------
__global__ __launch_bounds__(256) void ln_residual_kernel(
    const float2* __restrict__ h,
    const float2* __restrict__ ego,
    const float*  __restrict__ gamma,
    const float*  __restrict__ beta,
    float2*       __restrict__ out)
{
    int gt   = blockIdx.x * blockDim.x + threadIdx.x;
    int node = gt >> 5;
    int lane = threadIdx.x & 31;
    if (node >= N_NODES) return;

    int idx = node * 32 + lane;
    float2 v = h[idx];

    float s = v.x + v.y;
    #pragma unroll
    for (int o = 16; o; o >>= 1) s += __shfl_xor_sync(0xFFFFFFFFu, s, o);
    float mu = s * (1.f / 64.f);

    float dx = v.x - mu, dy = v.y - mu;
    float q = dx * dx + dy * dy;
    #pragma unroll
    for (int o = 16; o; o >>= 1) q += __shfl_xor_sync(0xFFFFFFFFu, q, o);
    float rstd = rsqrtf(q * (1.f / 64.f) + LN_EPS);

    float2 g = __ldg((const float2*)gamma + lane);
    float2 b = __ldg((const float2*)beta  + lane);
    float2 r = ego[idx];

    float2 o2;
    o2.x = dx * rstd * g.x + b.x + r.x;
    o2.y = dy * rstd * g.y + b.y + r.y;
    out[idx] = o2;
}

// ---------------------------------------------------------------------------
// Launch: 3 layers, each layer = zero+scatter(A^T) then zero+scatter(A).
// LeakyReLU of layer k's output is fused into layer k+1's gather.
// Last layer: LN + residual into d_out.
// ---------------------------------------------------------------------------
extern "C" void kernel_launch(void* const* d_in, const int* in_sizes, int n_in,
                              void* d_out, int out_size)
{
    const float* ego   = (const float*)d_in[0];
    const float* vals  = (const float*)d_in[1];
    const float* gamma = (const float*)d_in[2];
    const float* beta  = (const float*)d_in[3];
    const int*   rows  = (const int*)d_in[4];
    const int*   cols  = (const int*)d_in[5];
    float*       out   = (float*)d_out;

    float *tmp, *h;
    cudaGetSymbolAddress((void**)&tmp, g_tmp);
    cudaGetSymbolAddress((void**)&h,   g_h);

    const int n4      = N_NODES * 16;                 // float4 count of a node buffer
    const int zgrid   = (n4 + 255) / 256;
    const int sthreads = NE * 16;                     // 16 threads per edge
    const int sgrid   = (sthreads + 255) / 256;
    const int lngrid  = (N_NODES * 32 + 255) / 256;   // warp per node

    const float4* egov = (const float4*)ego;
    float4* tmp4 = (float4*)tmp;
    float4* h4   = (float4*)h;

    // ---- Layer 0:  h0 = A * (A^T * ego) ----
    zero_kernel<<<zgrid, 256>>>(tmp4, n4);
    spmm_scatter<false><<<sgrid, 256>>>(egov, vals, rows, cols, tmp4);   // t = A^T e
    zero_kernel<<<zgrid, 256>>>(h4, n4);
    spmm_scatter<false><<<sgrid, 256>>>((const float4*)tmp, vals, cols, rows, h4); // h = A t

    // ---- Layer 1:  h1 = A * (A^T * leaky(h0))  (leaky fused on gather) ----
    zero_kernel<<<zgrid, 256>>>(tmp4, n4);
    spmm_scatter<true ><<<sgrid, 256>>>((const float4*)h, vals, rows, cols, tmp4);
    zero_kernel<<<zgrid, 256>>>(h4, n4);
    spmm_scatter<false><<<sgrid, 256>>>((const float4*)tmp, vals, cols, rows, h4);

    // ---- Layer 2:  h2 = A * (A^T * leaky(h1)) ----
    zero_kernel<<<zgrid, 256>>>(tmp4, n4);
    spmm_scatter<true ><<<sgrid, 256>>>((const float4*)h, vals, rows, cols, tmp4);
    zero_kernel<<<zgrid, 256>>>(h4, n4);
    spmm_scatter<false><<<sgrid, 256>>>((const float4*)tmp, vals, cols, rows, h4);

    // ---- out = LN(h2)*gamma + beta + ego ----
    ln_residual_kernel<<<lngrid, 256>>>((const float2*)h, (const float2*)ego,
                                        gamma, beta, (float2*)out);
}

// round 2
// speedup vs baseline: 1.0032x; 1.0032x over previous
#include <cuda_runtime.h>
#include <cstdint>

// Problem constants (match reference_code)
#define N_NODES 150000
#define DIM 64
#define NE 4800000
#define LN_EPS 1e-5f
#define LEAKY_SLOPE 0.5f

// Scratch: two N x D fp32 buffers (38.4 MB each). __device__ globals => no allocation.
__device__ float g_tmp[(size_t)N_NODES * DIM];
__device__ float g_h[(size_t)N_NODES * DIM];

// ---------------------------------------------------------------------------
// Zero a buffer (float4-wide)
// ---------------------------------------------------------------------------
__global__ __launch_bounds__(256) void zero_kernel(float4* __restrict__ p, int n4) {
    int i = blockIdx.x * blockDim.x + threadIdx.x;
    if (i < n4) p[i] = make_float4(0.f, 0.f, 0.f, 0.f);
}

// ---------------------------------------------------------------------------
// Vectored fp32 reduction (sm_90+): 4 floats, one L2 atomic op, no return value
// ---------------------------------------------------------------------------
__device__ __forceinline__ void red_add_f32x4(float4* addr, float4 v) {
    asm volatile("red.global.add.v4.f32 [%0], {%1, %2, %3, %4};"
                 :: "l"(addr), "f"(v.x), "f"(v.y), "f"(v.z), "f"(v.w)
                 : "memory");
}

// ---------------------------------------------------------------------------
// Scatter SpMM:  y[dst[e]] += vals[e] * f(x[src[e]])   for all edges e
//   f = identity or LeakyReLU(0.5) applied to the gathered input (fused act)
//   16 threads per edge, one float4 per thread -> coalesced 256B row accesses
// ---------------------------------------------------------------------------
template <bool LEAKY_IN>
__global__ __launch_bounds__(256) void spmm_scatter(
    const float4* __restrict__ x,
    const float*  __restrict__ vals,
    const int*    __restrict__ src,
    const int*    __restrict__ dst,
    float4*       __restrict__ y)
{
    int t    = blockIdx.x * blockDim.x + threadIdx.x;   // < NE*16 = 76.8M, fits int
    int edge = t >> 4;
    int lane = t & 15;
    if (edge >= NE) return;

    int   s = __ldg(src  + edge);
    int   d = __ldg(dst  + edge);
    float v = __ldg(vals + edge);

    float4 xv = __ldg(x + s * 16 + lane);
    if (LEAKY_IN) {
        xv.x = xv.x > 0.f ? xv.x : LEAKY_SLOPE * xv.x;
        xv.y = xv.y > 0.f ? xv.y : LEAKY_SLOPE * xv.y;
        xv.z = xv.z > 0.f ? xv.z : LEAKY_SLOPE * xv.z;
        xv.w = xv.w > 0.f ? xv.w : LEAKY_SLOPE * xv.w;
    }
    float4 r = make_float4(v * xv.x, v * xv.y, v * xv.z, v * xv.w);
    red_add_f32x4(y + d * 16 + lane, r);
}

// ---------------------------------------------------------------------------
// Final: out = LayerNorm(h) * gamma + beta + ego        (warp per node, D=64)
// Each lane owns 2 columns (float2); mean/var via warp shuffles.
// ---------------------------------------------------------------------------
__global__ __launch_bounds__(256) void ln_residual_kernel(
    const float2* __restrict__ h,
    const float2* __restrict__ ego,
    const float*  __restrict__ gamma,
    const float*  __restrict__ beta,
    float2*       __restrict__ out)
{
    int gt   = blockIdx.x * blockDim.x + threadIdx.x;
    int node = gt >> 5;
    int lane = threadIdx.x & 31;
    if (node >= N_NODES) return;

    int idx = node * 32 + lane;
    float2 v = h[idx];

    float s = v.x + v.y;
    #pragma unroll
    for (int o = 16; o; o >>= 1) s += __shfl_xor_sync(0xFFFFFFFFu, s, o);
    float mu = s * (1.f / 64.f);

    float dx = v.x - mu, dy = v.y - mu;
    float q = dx * dx + dy * dy;
    #pragma unroll
    for (int o = 16; o; o >>= 1) q += __shfl_xor_sync(0xFFFFFFFFu, q, o);
    float rstd = rsqrtf(q * (1.f / 64.f) + LN_EPS);

    float2 g = __ldg((const float2*)gamma + lane);
    float2 b = __ldg((const float2*)beta  + lane);
    float2 r = ego[idx];

    float2 o2;
    o2.x = dx * rstd * g.x + b.x + r.x;
    o2.y = dy * rstd * g.y + b.y + r.y;
    out[idx] = o2;
}

// ---------------------------------------------------------------------------
// Launch: 3 layers, each layer = zero+scatter(A^T) then zero+scatter(A).
// LeakyReLU of layer k's output is fused into layer k+1's gather.
// Last layer: LN + residual into d_out.
// ---------------------------------------------------------------------------
extern "C" void kernel_launch(void* const* d_in, const int* in_sizes, int n_in,
                              void* d_out, int out_size)
{
    const float* ego   = (const float*)d_in[0];
    const float* vals  = (const float*)d_in[1];
    const float* gamma = (const float*)d_in[2];
    const float* beta  = (const float*)d_in[3];
    const int*   rows  = (const int*)d_in[4];
    const int*   cols  = (const int*)d_in[5];
    float*       out   = (float*)d_out;

    float *tmp, *h;
    cudaGetSymbolAddress((void**)&tmp, g_tmp);
    cudaGetSymbolAddress((void**)&h,   g_h);

    const int n4      = N_NODES * 16;                 // float4 count of a node buffer
    const int zgrid   = (n4 + 255) / 256;
    const int sthreads = NE * 16;                     // 16 threads per edge
    const int sgrid   = (sthreads + 255) / 256;
    const int lngrid  = (N_NODES * 32 + 255) / 256;   // warp per node

    const float4* egov = (const float4*)ego;
    float4* tmp4 = (float4*)tmp;
    float4* h4   = (float4*)h;

    // ---- Layer 0:  h0 = A * (A^T * ego) ----
    zero_kernel<<<zgrid, 256>>>(tmp4, n4);
    spmm_scatter<false><<<sgrid, 256>>>(egov, vals, rows, cols, tmp4);   // t = A^T e
    zero_kernel<<<zgrid, 256>>>(h4, n4);
    spmm_scatter<false><<<sgrid, 256>>>((const float4*)tmp, vals, cols, rows, h4); // h = A t

    // ---- Layer 1:  h1 = A * (A^T * leaky(h0))  (leaky fused on gather) ----
    zero_kernel<<<zgrid, 256>>>(tmp4, n4);
    spmm_scatter<true ><<<sgrid, 256>>>((const float4*)h, vals, rows, cols, tmp4);
    zero_kernel<<<zgrid, 256>>>(h4, n4);
    spmm_scatter<false><<<sgrid, 256>>>((const float4*)tmp, vals, cols, rows, h4);

    // ---- Layer 2:  h2 = A * (A^T * leaky(h1)) ----
    zero_kernel<<<zgrid, 256>>>(tmp4, n4);
    spmm_scatter<true ><<<sgrid, 256>>>((const float4*)h, vals, rows, cols, tmp4);
    zero_kernel<<<zgrid, 256>>>(h4, n4);
    spmm_scatter<false><<<sgrid, 256>>>((const float4*)tmp, vals, cols, rows, h4);

    // ---- out = LN(h2)*gamma + beta + ego ----
    ln_residual_kernel<<<lngrid, 256>>>((const float2*)h, (const float2*)ego,
                                        gamma, beta, (float2*)out);
}

// round 3
// speedup vs baseline: 2.3732x; 2.3657x over previous
#include <cuda_runtime.h>
#include <cstdint>

// Problem constants (match reference_code)
#define N_NODES 150000
#define DIM 64
#define NE 4800000
#define LN_EPS 1e-5f
#define LEAKY_SLOPE 0.5f
#define SCAN_B 1024
#define NB 147            // ceil(150000/1024)

// ---------------- device scratch (no allocation allowed) -------------------
__device__ float g_tmp[(size_t)N_NODES * DIM];   // 38.4 MB
__device__ float g_h  [(size_t)N_NODES * DIM];   // 38.4 MB

__device__ int   g_cnt_r[N_NODES], g_cnt_c[N_NODES];
__device__ int   g_ptr_r[N_NODES], g_ptr_c[N_NODES];
__device__ int   g_cur_r[N_NODES], g_cur_c[N_NODES];
__device__ int   g_bsum_r[NB], g_bsum_c[NB];
__device__ int   g_nbr_r[NE], g_nbr_c[NE];       // 19.2 MB each
__device__ float g_val_r[NE], g_val_c[NE];       // 19.2 MB each

// ---------------------------------------------------------------------------
// CSR build step 1: zero both count arrays
// ---------------------------------------------------------------------------
__global__ __launch_bounds__(256) void zero_counts(int* __restrict__ a, int* __restrict__ b) {
    int i = blockIdx.x * blockDim.x + threadIdx.x;
    if (i < N_NODES) { a[i] = 0; b[i] = 0; }
}

// step 2: histogram of rows and cols in one pass
__global__ __launch_bounds__(256) void hist_kernel(
    const int* __restrict__ rows, const int* __restrict__ cols,
    int* __restrict__ cnt_r, int* __restrict__ cnt_c)
{
    int e = blockIdx.x * blockDim.x + threadIdx.x;
    if (e >= NE) return;
    atomicAdd(cnt_r + __ldg(rows + e), 1);
    atomicAdd(cnt_c + __ldg(cols + e), 1);
}

// step 3a: per-block exclusive scan (Hillis-Steele in shared)
__global__ __launch_bounds__(SCAN_B) void scan1(
    const int* __restrict__ cnt, int* __restrict__ excl, int* __restrict__ bsum)
{
    __shared__ int sh[SCAN_B];
    int tid = threadIdx.x;
    int i   = blockIdx.x * SCAN_B + tid;
    int v   = (i < N_NODES) ? cnt[i] : 0;
    sh[tid] = v;
    __syncthreads();
    #pragma unroll
    for (int off = 1; off < SCAN_B; off <<= 1) {
        int t = (tid >= off) ? sh[tid - off] : 0;
        __syncthreads();
        sh[tid] += t;
        __syncthreads();
    }
    if (i < N_NODES) excl[i] = sh[tid] - v;
    if (tid == SCAN_B - 1) bsum[blockIdx.x] = sh[tid];
}

// step 3b: exclusive scan of the 147 block sums (single block)
__global__ __launch_bounds__(256) void scan2(int* __restrict__ bsum) {
    __shared__ int sh[256];
    int tid = threadIdx.x;
    int v   = (tid < NB) ? bsum[tid] : 0;
    sh[tid] = v;
    __syncthreads();
    #pragma unroll
    for (int off = 1; off < 256; off <<= 1) {
        int t = (tid >= off) ? sh[tid - off] : 0;
        __syncthreads();
        sh[tid] += t;
        __syncthreads();
    }
    if (tid < NB) bsum[tid] = sh[tid] - v;
}

// step 3c: add block offsets; also init the fill cursors
__global__ __launch_bounds__(256) void scan3(
    int* __restrict__ excl, const int* __restrict__ bsum, int* __restrict__ cursor)
{
    int i = blockIdx.x * blockDim.x + threadIdx.x;
    if (i >= N_NODES) return;
    int v = excl[i] + bsum[i >> 10];
    excl[i]   = v;
    cursor[i] = v;
}

// step 4: scatter edges into both CSR orderings (vals & neighbor permuted in)
__global__ __launch_bounds__(256) void fill_kernel(
    const int* __restrict__ rows, const int* __restrict__ cols,
    const float* __restrict__ vals,
    int* __restrict__ cur_r, int* __restrict__ cur_c,
    int* __restrict__ nbr_r, float* __restrict__ val_r,
    int* __restrict__ nbr_c, float* __restrict__ val_c)
{
    int e = blockIdx.x * blockDim.x + threadIdx.x;
    if (e >= NE) return;
    int   r = __ldg(rows + e);
    int   c = __ldg(cols + e);
    float v = __ldg(vals + e);
    int pr = atomicAdd(cur_r + r, 1);
    nbr_r[pr] = c;  val_r[pr] = v;
    int pc = atomicAdd(cur_c + c, 1);
    nbr_c[pc] = r;  val_c[pc] = v;
}

// ---------------------------------------------------------------------------
// Gather SpMM: y[n] = Σ_{j∈adj(n)} val[j] * f(x[nbr[j]])
//   16 threads per node, one float4 lane each -> 256B coalesced row accesses.
//   No atomics, no zero pass.
// ---------------------------------------------------------------------------
template <bool LEAKY_IN>
__global__ __launch_bounds__(256) void spmm_gather(
    const float4* __restrict__ x,
    const int*    __restrict__ ptr,
    const int*    __restrict__ cnt,
    const int*    __restrict__ nbr,
    const float*  __restrict__ val,
    float4*       __restrict__ y)
{
    int t    = blockIdx.x * blockDim.x + threadIdx.x;
    int node = t >> 4;
    int lane = t & 15;
    if (node >= N_NODES) return;

    int beg = __ldg(ptr + node);
    int end = beg + __ldg(cnt + node);

    float4 acc = make_float4(0.f, 0.f, 0.f, 0.f);
    for (int j = beg; j < end; ++j) {
        int   c = __ldg(nbr + j);
        float v = __ldg(val + j);
        float4 xv = __ldg(x + c * 16 + lane);
        if (LEAKY_IN) {
            xv.x = xv.x > 0.f ? xv.x : LEAKY_SLOPE * xv.x;
            xv.y = xv.y > 0.f ? xv.y : LEAKY_SLOPE * xv.y;
            xv.z = xv.z > 0.f ? xv.z : LEAKY_SLOPE * xv.z;
            xv.w = xv.w > 0.f ? xv.w : LEAKY_SLOPE * xv.w;
        }
        acc.x = fmaf(v, xv.x, acc.x);
        acc.y = fmaf(v, xv.y, acc.y);
        acc.z = fmaf(v, xv.z, acc.z);
        acc.w = fmaf(v, xv.w, acc.w);
    }
    y[node * 16 + lane] = acc;
}

// ---------------------------------------------------------------------------
// Final: out = LayerNorm(h) * gamma + beta + ego        (warp per node, D=64)
// ---------------------------------------------------------------------------
__global__ __launch_bounds__(256) void ln_residual_kernel(
    const float2* __restrict__ h,
    const float2* __restrict__ ego,
    const float*  __restrict__ gamma,
    const float*  __restrict__ beta,
    float2*       __restrict__ out)
{
    int gt   = blockIdx.x * blockDim.x + threadIdx.x;
    int node = gt >> 5;
    int lane = threadIdx.x & 31;
    if (node >= N_NODES) return;

    int idx = node * 32 + lane;
    float2 v = h[idx];

    float s = v.x + v.y;
    #pragma unroll
    for (int o = 16; o; o >>= 1) s += __shfl_xor_sync(0xFFFFFFFFu, s, o);
    float mu = s * (1.f / 64.f);

    float dx = v.x - mu, dy = v.y - mu;
    float q = dx * dx + dy * dy;
    #pragma unroll
    for (int o = 16; o; o >>= 1) q += __shfl_xor_sync(0xFFFFFFFFu, q, o);
    float rstd = rsqrtf(q * (1.f / 64.f) + LN_EPS);

    float2 g = __ldg((const float2*)gamma + lane);
    float2 b = __ldg((const float2*)beta  + lane);
    float2 r = ego[idx];

    float2 o2;
    o2.x = dx * rstd * g.x + b.x + r.x;
    o2.y = dy * rstd * g.y + b.y + r.y;
    out[idx] = o2;
}

// ---------------------------------------------------------------------------
extern "C" void kernel_launch(void* const* d_in, const int* in_sizes, int n_in,
                              void* d_out, int out_size)
{
    const float* ego   = (const float*)d_in[0];
    const float* vals  = (const float*)d_in[1];
    const float* gamma = (const float*)d_in[2];
    const float* beta  = (const float*)d_in[3];
    const int*   rows  = (const int*)d_in[4];
    const int*   cols  = (const int*)d_in[5];
    float*       out   = (float*)d_out;

    float *tmp, *h;  int *cnt_r, *cnt_c, *ptr_r, *ptr_c, *cur_r, *cur_c;
    int *bsum_r, *bsum_c, *nbr_r, *nbr_c;  float *val_r, *val_c;
    cudaGetSymbolAddress((void**)&tmp,    g_tmp);
    cudaGetSymbolAddress((void**)&h,      g_h);
    cudaGetSymbolAddress((void**)&cnt_r,  g_cnt_r);
    cudaGetSymbolAddress((void**)&cnt_c,  g_cnt_c);
    cudaGetSymbolAddress((void**)&ptr_r,  g_ptr_r);
    cudaGetSymbolAddress((void**)&ptr_c,  g_ptr_c);
    cudaGetSymbolAddress((void**)&cur_r,  g_cur_r);
    cudaGetSymbolAddress((void**)&cur_c,  g_cur_c);
    cudaGetSymbolAddress((void**)&bsum_r, g_bsum_r);
    cudaGetSymbolAddress((void**)&bsum_c, g_bsum_c);
    cudaGetSymbolAddress((void**)&nbr_r,  g_nbr_r);
    cudaGetSymbolAddress((void**)&nbr_c,  g_nbr_c);
    cudaGetSymbolAddress((void**)&val_r,  g_val_r);
    cudaGetSymbolAddress((void**)&val_c,  g_val_c);

    const int ngrid  = (N_NODES + 255) / 256;
    const int egrid  = (NE + 255) / 256;
    const int sgrid  = (N_NODES * 16 + 255) / 256;
    const int lngrid = (N_NODES * 32 + 255) / 256;

    // ---- Build both CSR orderings (reused by all 6 SpMMs) ----
    zero_counts<<<ngrid, 256>>>(cnt_r, cnt_c);
    hist_kernel<<<egrid, 256>>>(rows, cols, cnt_r, cnt_c);
    scan1<<<NB, SCAN_B>>>(cnt_r, ptr_r, bsum_r);
    scan1<<<NB, SCAN_B>>>(cnt_c, ptr_c, bsum_c);
    scan2<<<1, 256>>>(bsum_r);
    scan2<<<1, 256>>>(bsum_c);
    scan3<<<ngrid, 256>>>(ptr_r, bsum_r, cur_r);
    scan3<<<ngrid, 256>>>(ptr_c, bsum_c, cur_c);
    fill_kernel<<<egrid, 256>>>(rows, cols, vals, cur_r, cur_c,
                                nbr_r, val_r, nbr_c, val_c);

    const float4* egov = (const float4*)ego;
    float4* tmp4 = (float4*)tmp;
    float4* h4   = (float4*)h;

    // ---- Layer 0: h0 = A * (A^T * ego) ----
    // A^T*x groups by cols -> CSR_c (neighbors are rows); A*x groups by rows -> CSR_r.
    spmm_gather<false><<<sgrid, 256>>>(egov, ptr_c, cnt_c, nbr_c, val_c, tmp4);
    spmm_gather<false><<<sgrid, 256>>>((const float4*)tmp, ptr_r, cnt_r, nbr_r, val_r, h4);

    // ---- Layer 1: h1 = A * (A^T * leaky(h0)) ----
    spmm_gather<true ><<<sgrid, 256>>>((const float4*)h, ptr_c, cnt_c, nbr_c, val_c, tmp4);
    spmm_gather<false><<<sgrid, 256>>>((const float4*)tmp, ptr_r, cnt_r, nbr_r, val_r, h4);

    // ---- Layer 2: h2 = A * (A^T * leaky(h1)) ----
    spmm_gather<true ><<<sgrid, 256>>>((const float4*)h, ptr_c, cnt_c, nbr_c, val_c, tmp4);
    spmm_gather<false><<<sgrid, 256>>>((const float4*)tmp, ptr_r, cnt_r, nbr_r, val_r, h4);

    // ---- out = LN(h2)*gamma + beta + ego ----
    ln_residual_kernel<<<lngrid, 256>>>((const float2*)h, (const float2*)ego,
                                        gamma, beta, (float2*)out);
}

// round 5
// speedup vs baseline: 2.7821x; 1.1723x over previous
#include <cuda_runtime.h>
#include <cuda_fp16.h>
#include <cstdint>

// Problem constants (match reference_code)
#define N_NODES 150000
#define DIM 64
#define NE 4800000
#define LN_EPS 1e-5f
#define LEAKY_SLOPE 0.5f
#define SCAN_B 1024
#define NB 147            // ceil(150000/1024)

// Per-SpMM scale folded into edge weights so fp16 intermediates never overflow.
// 6 SpMMs => final h is (1/16)^6 = 2^-24 of true value; LN kernel undoes it.
#define VAL_SCALE  0.0625f          // 1/16
#define UNSCALE    16777216.0f      // 2^24

// ---------------- device scratch (no allocation allowed) -------------------
__device__ __align__(16) __half g_tmp_h[(size_t)N_NODES * DIM];
__device__ __align__(16) __half g_hh   [(size_t)N_NODES * DIM];
__device__ __align__(16) __half g_ego_h[(size_t)N_NODES * DIM];

__device__ int  g_cnt_r[N_NODES], g_cnt_c[N_NODES];
__device__ int  g_ptr_r[N_NODES], g_ptr_c[N_NODES];
__device__ int  g_cur_r[N_NODES], g_cur_c[N_NODES];
__device__ int  g_bsum_r[NB], g_bsum_c[NB];
// packed edges: {nbr:int, val_bits:int} = 8 B
__device__ __align__(8) int2 g_edge_r[NE];
__device__ __align__(8) int2 g_edge_c[NE];

// ---------------------------------------------------------------------------
__global__ __launch_bounds__(256) void zero_counts(int* __restrict__ a, int* __restrict__ b) {
    int i = blockIdx.x * blockDim.x + threadIdx.x;
    if (i < N_NODES) { a[i] = 0; b[i] = 0; }
}

__global__ __launch_bounds__(256) void hist_kernel(
    const int* __restrict__ rows, const int* __restrict__ cols,
    int* __restrict__ cnt_r, int* __restrict__ cnt_c)
{
    int e = blockIdx.x * blockDim.x + threadIdx.x;
    if (e >= NE) return;
    atomicAdd(cnt_r + __ldg(rows + e), 1);
    atomicAdd(cnt_c + __ldg(cols + e), 1);
}

__global__ __launch_bounds__(SCAN_B) void scan1(
    const int* __restrict__ cnt, int* __restrict__ excl, int* __restrict__ bsum)
{
    __shared__ int sh[SCAN_B];
    int tid = threadIdx.x;
    int i   = blockIdx.x * SCAN_B + tid;
    int v   = (i < N_NODES) ? cnt[i] : 0;
    sh[tid] = v;
    __syncthreads();
    #pragma unroll
    for (int off = 1; off < SCAN_B; off <<= 1) {
        int t = (tid >= off) ? sh[tid - off] : 0;
        __syncthreads();
        sh[tid] += t;
        __syncthreads();
    }
    if (i < N_NODES) excl[i] = sh[tid] - v;
    if (tid == SCAN_B - 1) bsum[blockIdx.x] = sh[tid];
}

__global__ __launch_bounds__(256) void scan2(int* __restrict__ bsum) {
    __shared__ int sh[256];
    int tid = threadIdx.x;
    int v   = (tid < NB) ? bsum[tid] : 0;
    sh[tid] = v;
    __syncthreads();
    #pragma unroll
    for (int off = 1; off < 256; off <<= 1) {
        int t = (tid >= off) ? sh[tid - off] : 0;
        __syncthreads();
        sh[tid] += t;
        __syncthreads();
    }
    if (tid < NB) bsum[tid] = sh[tid] - v;
}

__global__ __launch_bounds__(256) void scan3(
    int* __restrict__ excl, const int* __restrict__ bsum, int* __restrict__ cursor)
{
    int i = blockIdx.x * blockDim.x + threadIdx.x;
    if (i >= N_NODES) return;
    int v = excl[i] + bsum[i >> 10];
    excl[i]   = v;
    cursor[i] = v;
}

// scatter packed edges; fold the per-SpMM 1/16 scale into the stored weight
__global__ __launch_bounds__(256) void fill_kernel(
    const int* __restrict__ rows, const int* __restrict__ cols,
    const float* __restrict__ vals,
    int* __restrict__ cur_r, int* __restrict__ cur_c,
    int2* __restrict__ edge_r, int2* __restrict__ edge_c)
{
    int e = blockIdx.x * blockDim.x + threadIdx.x;
    if (e >= NE) return;
    int r = __ldg(rows + e);
    int c = __ldg(cols + e);
    int v = __float_as_int(__ldg(vals + e) * VAL_SCALE);
    int pr = atomicAdd(cur_r + r, 1);
    edge_r[pr] = make_int2(c, v);
    int pc = atomicAdd(cur_c + c, 1);
    edge_c[pc] = make_int2(r, v);
}

// ---------------------------------------------------------------------------
__global__ __launch_bounds__(256) void cvt_f32_f16(
    const float4* __restrict__ in, uint2* __restrict__ out, int n4)
{
    int i = blockIdx.x * blockDim.x + threadIdx.x;
    if (i >= n4) return;
    float4 f = __ldg(in + i);
    __half2 a = __floats2half2_rn(f.x, f.y);
    __half2 b = __floats2half2_rn(f.z, f.w);
    uint2 o;
    o.x = *reinterpret_cast<unsigned int*>(&a);
    o.y = *reinterpret_cast<unsigned int*>(&b);
    out[i] = o;
}

// ---------------------------------------------------------------------------
// Gather SpMM (fp16 node data, fp32 accumulate), 16 threads/node, 8 B/lane
// ---------------------------------------------------------------------------
template <bool LEAKY_IN>
__global__ __launch_bounds__(256) void spmm_gather_h(
    const uint2* __restrict__ x,
    const int*   __restrict__ ptr,
    const int*   __restrict__ cnt,
    const int2*  __restrict__ edges,
    uint2*       __restrict__ y)
{
    int t    = blockIdx.x * blockDim.x + threadIdx.x;
    int node = t >> 4;
    int lane = t & 15;
    if (node >= N_NODES) return;

    int beg = __ldg(ptr + node);
    int end = beg + __ldg(cnt + node);

    float a0 = 0.f, a1 = 0.f, a2 = 0.f, a3 = 0.f;
    for (int j = beg; j < end; ++j) {
        int2  e = __ldg(edges + j);
        float v = __int_as_float(e.y);
        uint2 p = __ldg(x + e.x * 16 + lane);
        __half2 h0 = *reinterpret_cast<__half2*>(&p.x);
        __half2 h1 = *reinterpret_cast<__half2*>(&p.y);
        float2 f0 = __half22float2(h0);
        float2 f1 = __half22float2(h1);
        if (LEAKY_IN) {
            f0.x = f0.x > 0.f ? f0.x : LEAKY_SLOPE * f0.x;
            f0.y = f0.y > 0.f ? f0.y : LEAKY_SLOPE * f0.y;
            f1.x = f1.x > 0.f ? f1.x : LEAKY_SLOPE * f1.x;
            f1.y = f1.y > 0.f ? f1.y : LEAKY_SLOPE * f1.y;
        }
        a0 = fmaf(v, f0.x, a0);
        a1 = fmaf(v, f0.y, a1);
        a2 = fmaf(v, f1.x, a2);
        a3 = fmaf(v, f1.y, a3);
    }
    __half2 o0 = __floats2half2_rn(a0, a1);
    __half2 o1 = __floats2half2_rn(a2, a3);
    uint2 o;
    o.x = *reinterpret_cast<unsigned int*>(&o0);
    o.y = *reinterpret_cast<unsigned int*>(&o1);
    y[node * 16 + lane] = o;
}

// ---------------------------------------------------------------------------
// Final: out = LN(h * 2^24) * gamma + beta + ego   (warp per node, D=64)
// The 2^24 undoes the six folded 1/16 edge scales so LN's eps acts at the
// reference magnitude.
// ---------------------------------------------------------------------------
__global__ __launch_bounds__(256) void ln_residual_kernel(
    const __half2* __restrict__ h,
    const float2*  __restrict__ ego,
    const float*   __restrict__ gamma,
    const float*   __restrict__ beta,
    float2*        __restrict__ out)
{
    int gt   = blockIdx.x * blockDim.x + threadIdx.x;
    int node = gt >> 5;
    int lane = threadIdx.x & 31;
    if (node >= N_NODES) return;

    int idx = node * 32 + lane;
    float2 v = __half22float2(h[idx]);
    v.x *= UNSCALE;
    v.y *= UNSCALE;

    float s = v.x + v.y;
    #pragma unroll
    for (int o = 16; o; o >>= 1) s += __shfl_xor_sync(0xFFFFFFFFu, s, o);
    float mu = s * (1.f / 64.f);

    float dx = v.x - mu, dy = v.y - mu;
    float q = dx * dx + dy * dy;
    #pragma unroll
    for (int o = 16; o; o >>= 1) q += __shfl_xor_sync(0xFFFFFFFFu, q, o);
    float rstd = rsqrtf(q * (1.f / 64.f) + LN_EPS);

    float2 g = __ldg((const float2*)gamma + lane);
    float2 b = __ldg((const float2*)beta  + lane);
    float2 r = ego[idx];

    float2 o2;
    o2.x = dx * rstd * g.x + b.x + r.x;
    o2.y = dy * rstd * g.y + b.y + r.y;
    out[idx] = o2;
}

// ---------------------------------------------------------------------------
extern "C" void kernel_launch(void* const* d_in, const int* in_sizes, int n_in,
                              void* d_out, int out_size)
{
    const float* ego   = (const float*)d_in[0];
    const float* vals  = (const float*)d_in[1];
    const float* gamma = (const float*)d_in[2];
    const float* beta  = (const float*)d_in[3];
    const int*   rows  = (const int*)d_in[4];
    const int*   cols  = (const int*)d_in[5];
    float*       out   = (float*)d_out;

    void *tmp_h, *hh, *ego_h;
    int *cnt_r, *cnt_c, *ptr_r, *ptr_c, *cur_r, *cur_c, *bsum_r, *bsum_c;
    int2 *edge_r, *edge_c;
    cudaGetSymbolAddress(&tmp_h, g_tmp_h);
    cudaGetSymbolAddress(&hh,    g_hh);
    cudaGetSymbolAddress(&ego_h, g_ego_h);
    cudaGetSymbolAddress((void**)&cnt_r,  g_cnt_r);
    cudaGetSymbolAddress((void**)&cnt_c,  g_cnt_c);
    cudaGetSymbolAddress((void**)&ptr_r,  g_ptr_r);
    cudaGetSymbolAddress((void**)&ptr_c,  g_ptr_c);
    cudaGetSymbolAddress((void**)&cur_r,  g_cur_r);
    cudaGetSymbolAddress((void**)&cur_c,  g_cur_c);
    cudaGetSymbolAddress((void**)&bsum_r, g_bsum_r);
    cudaGetSymbolAddress((void**)&bsum_c, g_bsum_c);
    cudaGetSymbolAddress((void**)&edge_r, g_edge_r);
    cudaGetSymbolAddress((void**)&edge_c, g_edge_c);

    const int ngrid  = (N_NODES + 255) / 256;
    const int egrid  = (NE + 255) / 256;
    const int sgrid  = (N_NODES * 16 + 255) / 256;
    const int lngrid = (N_NODES * 32 + 255) / 256;
    const int cvt_n4 = N_NODES * DIM / 4;
    const int cgrid  = (cvt_n4 + 255) / 256;

    // ---- Build both CSR orderings (reused by all 6 SpMMs) ----
    zero_counts<<<ngrid, 256>>>(cnt_r, cnt_c);
    hist_kernel<<<egrid, 256>>>(rows, cols, cnt_r, cnt_c);
    scan1<<<NB, SCAN_B>>>(cnt_r, ptr_r, bsum_r);
    scan1<<<NB, SCAN_B>>>(cnt_c, ptr_c, bsum_c);
    scan2<<<1, 256>>>(bsum_r);
    scan2<<<1, 256>>>(bsum_c);
    scan3<<<ngrid, 256>>>(ptr_r, bsum_r, cur_r);
    scan3<<<ngrid, 256>>>(ptr_c, bsum_c, cur_c);
    fill_kernel<<<egrid, 256>>>(rows, cols, vals, cur_r, cur_c, edge_r, edge_c);

    // ---- ego -> fp16 ----
    cvt_f32_f16<<<cgrid, 256>>>((const float4*)ego, (uint2*)ego_h, cvt_n4);

    const uint2* egoh = (const uint2*)ego_h;
    uint2* tmp4 = (uint2*)tmp_h;
    uint2* h4   = (uint2*)hh;

    // ---- Layer 0: h0 = A * (A^T * ego) ----
    spmm_gather_h<false><<<sgrid, 256>>>(egoh, ptr_c, cnt_c, edge_c, tmp4);
    spmm_gather_h<false><<<sgrid, 256>>>((const uint2*)tmp_h, ptr_r, cnt_r, edge_r, h4);

    // ---- Layer 1: h1 = A * (A^T * leaky(h0)) ----
    spmm_gather_h<true ><<<sgrid, 256>>>((const uint2*)hh, ptr_c, cnt_c, edge_c, tmp4);
    spmm_gather_h<false><<<sgrid, 256>>>((const uint2*)tmp_h, ptr_r, cnt_r, edge_r, h4);

    // ---- Layer 2: h2 = A * (A^T * leaky(h1)) ----
    spmm_gather_h<true ><<<sgrid, 256>>>((const uint2*)hh, ptr_c, cnt_c, edge_c, tmp4);
    spmm_gather_h<false><<<sgrid, 256>>>((const uint2*)tmp_h, ptr_r, cnt_r, edge_r, h4);

    // ---- out = LN(h2 * 2^24)*gamma + beta + ego ----
    ln_residual_kernel<<<lngrid, 256>>>((const __half2*)hh, (const float2*)ego,
                                        gamma, beta, (float2*)out);
}

// round 6
// speedup vs baseline: 3.0130x; 1.0830x over previous
#include <cuda_runtime.h>
#include <cuda_fp16.h>
#include <cstdint>

// Problem constants (match reference_code)
#define N_NODES 150000
#define DIM 64
#define NE 4800000
#define LN_EPS 1e-5f
#define LEAKY_SLOPE 0.5f
#define SCAN_B 1024
#define NB 147            // ceil(150000/1024)

// Per-SpMM scale folded into edge weights so fp16 intermediates never overflow.
// 6 SpMMs => final h is (1/16)^6 = 2^-24 of true value; LN kernel undoes it.
#define VAL_SCALE  0.0625f          // 1/16
#define UNSCALE    16777216.0f      // 2^24

// ---------------- device scratch (no allocation allowed) -------------------
__device__ __align__(16) __half g_tmp_h[(size_t)N_NODES * DIM];
__device__ __align__(16) __half g_hh   [(size_t)N_NODES * DIM];
__device__ __align__(16) __half g_ego_h[(size_t)N_NODES * DIM];

__device__ int  g_cnt_r[N_NODES], g_cnt_c[N_NODES];
__device__ int  g_ptr_r[N_NODES], g_ptr_c[N_NODES];
__device__ int  g_cur_r[N_NODES], g_cur_c[N_NODES];
__device__ int  g_bsum_r[NB], g_bsum_c[NB];
// packed edges: {nbr:int, val_bits:int} = 8 B
__device__ __align__(8) int2 g_edge_r[NE];
__device__ __align__(8) int2 g_edge_c[NE];

// ---------------------------------------------------------------------------
__global__ __launch_bounds__(256) void zero_counts(int* __restrict__ a, int* __restrict__ b) {
    int i = blockIdx.x * blockDim.x + threadIdx.x;
    if (i < N_NODES) { a[i] = 0; b[i] = 0; }
}

__global__ __launch_bounds__(256) void hist_kernel(
    const int* __restrict__ rows, const int* __restrict__ cols,
    int* __restrict__ cnt_r, int* __restrict__ cnt_c)
{
    int e = blockIdx.x * blockDim.x + threadIdx.x;
    if (e >= NE) return;
    atomicAdd(cnt_r + __ldg(rows + e), 1);
    atomicAdd(cnt_c + __ldg(cols + e), 1);
}

__global__ __launch_bounds__(SCAN_B) void scan1(
    const int* __restrict__ cnt, int* __restrict__ excl, int* __restrict__ bsum)
{
    __shared__ int sh[SCAN_B];
    int tid = threadIdx.x;
    int i   = blockIdx.x * SCAN_B + tid;
    int v   = (i < N_NODES) ? cnt[i] : 0;
    sh[tid] = v;
    __syncthreads();
    #pragma unroll
    for (int off = 1; off < SCAN_B; off <<= 1) {
        int t = (tid >= off) ? sh[tid - off] : 0;
        __syncthreads();
        sh[tid] += t;
        __syncthreads();
    }
    if (i < N_NODES) excl[i] = sh[tid] - v;
    if (tid == SCAN_B - 1) bsum[blockIdx.x] = sh[tid];
}

__global__ __launch_bounds__(256) void scan2(int* __restrict__ bsum) {
    __shared__ int sh[256];
    int tid = threadIdx.x;
    int v   = (tid < NB) ? bsum[tid] : 0;
    sh[tid] = v;
    __syncthreads();
    #pragma unroll
    for (int off = 1; off < 256; off <<= 1) {
        int t = (tid >= off) ? sh[tid - off] : 0;
        __syncthreads();
        sh[tid] += t;
        __syncthreads();
    }
    if (tid < NB) bsum[tid] = sh[tid] - v;
}

__global__ __launch_bounds__(256) void scan3(
    int* __restrict__ excl, const int* __restrict__ bsum, int* __restrict__ cursor)
{
    int i = blockIdx.x * blockDim.x + threadIdx.x;
    if (i >= N_NODES) return;
    int v = excl[i] + bsum[i >> 10];
    excl[i]   = v;
    cursor[i] = v;
}

// scatter packed edges; fold the per-SpMM 1/16 scale into the stored weight
__global__ __launch_bounds__(256) void fill_kernel(
    const int* __restrict__ rows, const int* __restrict__ cols,
    const float* __restrict__ vals,
    int* __restrict__ cur_r, int* __restrict__ cur_c,
    int2* __restrict__ edge_r, int2* __restrict__ edge_c)
{
    int e = blockIdx.x * blockDim.x + threadIdx.x;
    if (e >= NE) return;
    int r = __ldg(rows + e);
    int c = __ldg(cols + e);
    int v = __float_as_int(__ldg(vals + e) * VAL_SCALE);
    int pr = atomicAdd(cur_r + r, 1);
    edge_r[pr] = make_int2(c, v);
    int pc = atomicAdd(cur_c + c, 1);
    edge_c[pc] = make_int2(r, v);
}

// ---------------------------------------------------------------------------
__global__ __launch_bounds__(256) void cvt_f32_f16(
    const float4* __restrict__ in, uint2* __restrict__ out, int n4)
{
    int i = blockIdx.x * blockDim.x + threadIdx.x;
    if (i >= n4) return;
    float4 f = __ldg(in + i);
    __half2 a = __floats2half2_rn(f.x, f.y);
    __half2 b = __floats2half2_rn(f.z, f.w);
    uint2 o;
    o.x = *reinterpret_cast<unsigned int*>(&a);
    o.y = *reinterpret_cast<unsigned int*>(&b);
    out[i] = o;
}

// ---------------------------------------------------------------------------
// Gather SpMM (fp16 node data, fp32 accumulate):
//   8 lanes per node, each lane owns 16 B (8 halves); 2-edge unrolled loop.
// ---------------------------------------------------------------------------
__device__ __forceinline__ void accum_u4(uint4 p, float v, bool leaky, float* a) {
    __half2 h0 = *reinterpret_cast<__half2*>(&p.x);
    __half2 h1 = *reinterpret_cast<__half2*>(&p.y);
    __half2 h2 = *reinterpret_cast<__half2*>(&p.z);
    __half2 h3 = *reinterpret_cast<__half2*>(&p.w);
    float2 f0 = __half22float2(h0);
    float2 f1 = __half22float2(h1);
    float2 f2 = __half22float2(h2);
    float2 f3 = __half22float2(h3);
    if (leaky) {
        f0.x = f0.x > 0.f ? f0.x : LEAKY_SLOPE * f0.x;
        f0.y = f0.y > 0.f ? f0.y : LEAKY_SLOPE * f0.y;
        f1.x = f1.x > 0.f ? f1.x : LEAKY_SLOPE * f1.x;
        f1.y = f1.y > 0.f ? f1.y : LEAKY_SLOPE * f1.y;
        f2.x = f2.x > 0.f ? f2.x : LEAKY_SLOPE * f2.x;
        f2.y = f2.y > 0.f ? f2.y : LEAKY_SLOPE * f2.y;
        f3.x = f3.x > 0.f ? f3.x : LEAKY_SLOPE * f3.x;
        f3.y = f3.y > 0.f ? f3.y : LEAKY_SLOPE * f3.y;
    }
    a[0] = fmaf(v, f0.x, a[0]);
    a[1] = fmaf(v, f0.y, a[1]);
    a[2] = fmaf(v, f1.x, a[2]);
    a[3] = fmaf(v, f1.y, a[3]);
    a[4] = fmaf(v, f2.x, a[4]);
    a[5] = fmaf(v, f2.y, a[5]);
    a[6] = fmaf(v, f3.x, a[6]);
    a[7] = fmaf(v, f3.y, a[7]);
}

template <bool LEAKY_IN>
__global__ __launch_bounds__(256) void spmm_gather_h8(
    const uint4* __restrict__ x,       // fp16 rows: node*8 + lane (16 B lanes)
    const int*   __restrict__ ptr,
    const int*   __restrict__ cnt,
    const int2*  __restrict__ edges,
    uint4*       __restrict__ y)
{
    int t    = blockIdx.x * blockDim.x + threadIdx.x;
    int node = t >> 3;
    int lane = t & 7;
    if (node >= N_NODES) return;

    int beg = __ldg(ptr + node);
    int end = beg + __ldg(cnt + node);

    float acc[8] = {0.f, 0.f, 0.f, 0.f, 0.f, 0.f, 0.f, 0.f};

    int j = beg;
    for (; j + 2 <= end; j += 2) {
        int2 e0 = __ldg(edges + j);
        int2 e1 = __ldg(edges + j + 1);
        uint4 p0 = __ldg(x + e0.x * 8 + lane);
        uint4 p1 = __ldg(x + e1.x * 8 + lane);
        accum_u4(p0, __int_as_float(e0.y), LEAKY_IN, acc);
        accum_u4(p1, __int_as_float(e1.y), LEAKY_IN, acc);
    }
    if (j < end) {
        int2 e0 = __ldg(edges + j);
        uint4 p0 = __ldg(x + e0.x * 8 + lane);
        accum_u4(p0, __int_as_float(e0.y), LEAKY_IN, acc);
    }

    __half2 o0 = __floats2half2_rn(acc[0], acc[1]);
    __half2 o1 = __floats2half2_rn(acc[2], acc[3]);
    __half2 o2 = __floats2half2_rn(acc[4], acc[5]);
    __half2 o3 = __floats2half2_rn(acc[6], acc[7]);
    uint4 o;
    o.x = *reinterpret_cast<unsigned int*>(&o0);
    o.y = *reinterpret_cast<unsigned int*>(&o1);
    o.z = *reinterpret_cast<unsigned int*>(&o2);
    o.w = *reinterpret_cast<unsigned int*>(&o3);
    y[node * 8 + lane] = o;
}

// ---------------------------------------------------------------------------
// Final: out = LN(h * 2^24) * gamma + beta + ego   (warp per node, D=64)
// ---------------------------------------------------------------------------
__global__ __launch_bounds__(256) void ln_residual_kernel(
    const __half2* __restrict__ h,
    const float2*  __restrict__ ego,
    const float*   __restrict__ gamma,
    const float*   __restrict__ beta,
    float2*        __restrict__ out)
{
    int gt   = blockIdx.x * blockDim.x + threadIdx.x;
    int node = gt >> 5;
    int lane = threadIdx.x & 31;
    if (node >= N_NODES) return;

    int idx = node * 32 + lane;
    float2 v = __half22float2(h[idx]);
    v.x *= UNSCALE;
    v.y *= UNSCALE;

    float s = v.x + v.y;
    #pragma unroll
    for (int o = 16; o; o >>= 1) s += __shfl_xor_sync(0xFFFFFFFFu, s, o);
    float mu = s * (1.f / 64.f);

    float dx = v.x - mu, dy = v.y - mu;
    float q = dx * dx + dy * dy;
    #pragma unroll
    for (int o = 16; o; o >>= 1) q += __shfl_xor_sync(0xFFFFFFFFu, q, o);
    float rstd = rsqrtf(q * (1.f / 64.f) + LN_EPS);

    float2 g = __ldg((const float2*)gamma + lane);
    float2 b = __ldg((const float2*)beta  + lane);
    float2 r = ego[idx];

    float2 o2;
    o2.x = dx * rstd * g.x + b.x + r.x;
    o2.y = dy * rstd * g.y + b.y + r.y;
    out[idx] = o2;
}

// ---------------------------------------------------------------------------
extern "C" void kernel_launch(void* const* d_in, const int* in_sizes, int n_in,
                              void* d_out, int out_size)
{
    const float* ego   = (const float*)d_in[0];
    const float* vals  = (const float*)d_in[1];
    const float* gamma = (const float*)d_in[2];
    const float* beta  = (const float*)d_in[3];
    const int*   rows  = (const int*)d_in[4];
    const int*   cols  = (const int*)d_in[5];
    float*       out   = (float*)d_out;

    void *tmp_h, *hh, *ego_h;
    int *cnt_r, *cnt_c, *ptr_r, *ptr_c, *cur_r, *cur_c, *bsum_r, *bsum_c;
    int2 *edge_r, *edge_c;
    cudaGetSymbolAddress(&tmp_h, g_tmp_h);
    cudaGetSymbolAddress(&hh,    g_hh);
    cudaGetSymbolAddress(&ego_h, g_ego_h);
    cudaGetSymbolAddress((void**)&cnt_r,  g_cnt_r);
    cudaGetSymbolAddress((void**)&cnt_c,  g_cnt_c);
    cudaGetSymbolAddress((void**)&ptr_r,  g_ptr_r);
    cudaGetSymbolAddress((void**)&ptr_c,  g_ptr_c);
    cudaGetSymbolAddress((void**)&cur_r,  g_cur_r);
    cudaGetSymbolAddress((void**)&cur_c,  g_cur_c);
    cudaGetSymbolAddress((void**)&bsum_r, g_bsum_r);
    cudaGetSymbolAddress((void**)&bsum_c, g_bsum_c);
    cudaGetSymbolAddress((void**)&edge_r, g_edge_r);
    cudaGetSymbolAddress((void**)&edge_c, g_edge_c);

    const int ngrid  = (N_NODES + 255) / 256;
    const int egrid  = (NE + 255) / 256;
    const int sgrid  = (N_NODES * 8 + 255) / 256;      // 8 lanes per node
    const int lngrid = (N_NODES * 32 + 255) / 256;
    const int cvt_n4 = N_NODES * DIM / 4;
    const int cgrid  = (cvt_n4 + 255) / 256;

    // ---- Build both CSR orderings (reused by all 6 SpMMs) ----
    zero_counts<<<ngrid, 256>>>(cnt_r, cnt_c);
    hist_kernel<<<egrid, 256>>>(rows, cols, cnt_r, cnt_c);
    scan1<<<NB, SCAN_B>>>(cnt_r, ptr_r, bsum_r);
    scan1<<<NB, SCAN_B>>>(cnt_c, ptr_c, bsum_c);
    scan2<<<1, 256>>>(bsum_r);
    scan2<<<1, 256>>>(bsum_c);
    scan3<<<ngrid, 256>>>(ptr_r, bsum_r, cur_r);
    scan3<<<ngrid, 256>>>(ptr_c, bsum_c, cur_c);
    fill_kernel<<<egrid, 256>>>(rows, cols, vals, cur_r, cur_c, edge_r, edge_c);

    // ---- ego -> fp16 ----
    cvt_f32_f16<<<cgrid, 256>>>((const float4*)ego, (uint2*)ego_h, cvt_n4);

    const uint4* egoh = (const uint4*)ego_h;
    uint4* tmp4 = (uint4*)tmp_h;
    uint4* h4   = (uint4*)hh;

    // ---- Layer 0: h0 = A * (A^T * ego) ----
    spmm_gather_h8<false><<<sgrid, 256>>>(egoh, ptr_c, cnt_c, edge_c, tmp4);
    spmm_gather_h8<false><<<sgrid, 256>>>((const uint4*)tmp_h, ptr_r, cnt_r, edge_r, h4);

    // ---- Layer 1: h1 = A * (A^T * leaky(h0)) ----
    spmm_gather_h8<true ><<<sgrid, 256>>>((const uint4*)hh, ptr_c, cnt_c, edge_c, tmp4);
    spmm_gather_h8<false><<<sgrid, 256>>>((const uint4*)tmp_h, ptr_r, cnt_r, edge_r, h4);

    // ---- Layer 2: h2 = A * (A^T * leaky(h1)) ----
    spmm_gather_h8<true ><<<sgrid, 256>>>((const uint4*)hh, ptr_c, cnt_c, edge_c, tmp4);
    spmm_gather_h8<false><<<sgrid, 256>>>((const uint4*)tmp_h, ptr_r, cnt_r, edge_r, h4);

    // ---- out = LN(h2 * 2^24)*gamma + beta + ego ----
    ln_residual_kernel<<<lngrid, 256>>>((const __half2*)hh, (const float2*)ego,
                                        gamma, beta, (float2*)out);
}